// round 13
// baseline (speedup 1.0000x reference)
#include <cuda_runtime.h>
#include <cuda_bf16.h>
#include <math.h>
#include <stdint.h>

// Problem constants
#define B_ 2
#define N_ 12288
#define D_ 256
#define NW (N_ / 32)            // bitmask words per row = 384
#define NT (N_ / 128)           // 128-wide tiles per batch = 96
#define CONF_THRESH 0.8f
#define JSPLIT 3
// bf16 mma sim abs error bound ~0.0044:
#define CAND_T    0.7925f       // flag threshold (abs)
#define SKIP_M    0.7956f       // row skip: m <= SKIP_M => true max <= 0.8
// bucket-rescore capacities
#define BK_ROWS 256
#define BK_COLS 128

// ---------------- device scratch (no allocations allowed) ----------------
__device__ __align__(128) uint4 g_Vt[(size_t)B_ * NT * 4096];
__device__ __align__(128) uint4 g_Rt[(size_t)B_ * NT * 4096];
__device__ float    g_Vf[(size_t)B_ * N_ * D_];
__device__ float    g_Rf[(size_t)B_ * N_ * D_];
__device__ unsigned g_bm[(size_t)B_ * N_ * NW];   // candidate bitmask
__device__ int      g_bcnt[B_ * N_];              // bucket counts (rep col)
__device__ unsigned short g_blist[(size_t)B_ * N_ * BK_ROWS];
__device__ unsigned char  g_oflow[B_ * N_];       // fallback flags
__device__ int      g_nval[B_];
__device__ int      g_ninv[B_];
__device__ int      g_nconf[B_];
__device__ unsigned g_rmax[B_ * N_];     // monotonic-encoded approx row max
__device__ double   g_contrib[B_];
__device__ int      g_mask_mode;         // 0=int32, 1=uint8, 2=float32

// SMEM layout (p1, bytes)
#define SM_A    0u
#define SM_B    65536u
#define SM_MAX  196608u
#define SM_MBAR 198656u
#define SMEM_BYTES 198720
// bucket kernel dynamic smem: colbuf 128*1KB + union 1536 + slist 256
#define BSM_BYTES (131072 + 1536 + 256)

// ---------------- small helpers ----------------
__device__ __forceinline__ uint32_t smem_u32_addr(const void* p) {
    uint32_t a;
    asm("{ .reg .u64 t; cvta.to.shared.u64 t, %1; cvt.u32.u64 %0, t; }"
        : "=r"(a) : "l"(p));
    return a;
}
__device__ __forceinline__ uint32_t sw128(uint32_t off) {
    return off ^ ((off >> 3) & 0x70u);
}
__device__ __forceinline__ uint32_t img_off(int c, int ku) {
    return (uint32_t)((c >> 3) * 4 + (ku >> 3)) * 1024u
         + (uint32_t)(c & 7) * 128u + (uint32_t)(ku & 7) * 16u;
}
__device__ __forceinline__ void ldmatrix_x4(uint32_t* r, uint32_t addr) {
    asm volatile("ldmatrix.sync.aligned.m8n8.x4.shared.b16 {%0,%1,%2,%3}, [%4];"
                 : "=r"(r[0]), "=r"(r[1]), "=r"(r[2]), "=r"(r[3]) : "r"(addr));
}
__device__ __forceinline__ void mma16816(float* c, const uint32_t* a,
                                         uint32_t b0, uint32_t b1) {
    asm volatile(
        "mma.sync.aligned.m16n8k16.row.col.f32.bf16.bf16.f32 "
        "{%0,%1,%2,%3}, {%4,%5,%6,%7}, {%8,%9}, {%0,%1,%2,%3};"
        : "+f"(c[0]), "+f"(c[1]), "+f"(c[2]), "+f"(c[3])
        : "r"(a[0]), "r"(a[1]), "r"(a[2]), "r"(a[3]), "r"(b0), "r"(b1));
}
#define MBAR_INIT(mbar, cnt) \
    asm volatile("mbarrier.init.shared.b64 [%0], %1;" \
                 :: "r"(mbar), "r"((uint32_t)(cnt)) : "memory")
#define MBAR_EXPECT_TX(mbar, tx) \
    asm volatile("mbarrier.arrive.expect_tx.shared.b64 _, [%0], %1;" \
                 :: "r"(mbar), "r"((uint32_t)(tx)) : "memory")
__device__ __forceinline__ void bulk_ldg(uint32_t sdst, const void* gsrc,
                                         uint32_t bytes, uint32_t mbar) {
    asm volatile(
        "cp.async.bulk.shared::cluster.global.mbarrier::complete_tx::bytes "
        "[%0], [%1], %2, [%3];"
        :: "r"(sdst), "l"(gsrc), "r"(bytes), "r"(mbar) : "memory");
}
#define MBAR_WAIT_PARITY(mbar, par) do {                                           \
    uint32_t _m = (mbar); uint32_t _p = (uint32_t)(par); uint32_t _d;              \
    asm volatile("{ .reg .pred p; "                                                \
        "mbarrier.try_wait.parity.acquire.cta.shared::cta.b64 p, [%1], %2; "       \
        "selp.b32 %0, 1, 0, p; }" : "=r"(_d) : "r"(_m), "r"(_p) : "memory");       \
    if (!_d) {                                                                     \
        asm volatile("{ .reg .pred P1; "                                           \
            "WL_%=: mbarrier.try_wait.parity.acquire.cta.shared::cta.b64 P1, [%0], %1, 0x989680; " \
            "@P1 bra.uni WD_%=; bra.uni WL_%=; WD_%=: }"                           \
            :: "r"(_m), "r"(_p) : "memory");                                       \
    }                                                                              \
} while (0)
__device__ __forceinline__ unsigned enc_max(float m) {
    int rep = __float_as_int(m);
    return (rep < 0) ? ~((unsigned)rep) : ((unsigned)rep | 0x80000000u);
}
__device__ __forceinline__ float dec_max(unsigned key) {
    return (key & 0x80000000u) ? __uint_as_float(key & 0x7fffffffu)
                               : __uint_as_float(~key);
}
// warp-cooperative exact dot: row fragment in r0/r1, col via float4 base
__device__ __forceinline__ float dot8(float4 x0, float4 x1,
                                      float4 r0, float4 r1) {
    float s = 0.0f;
    s = fmaf(x0.x, r0.x, s); s = fmaf(x0.y, r0.y, s);
    s = fmaf(x0.z, r0.z, s); s = fmaf(x0.w, r0.w, s);
    s = fmaf(x1.x, r1.x, s); s = fmaf(x1.y, r1.y, s);
    s = fmaf(x1.z, r1.z, s); s = fmaf(x1.w, r1.w, s);
    return s;
}

// ---------------- init ----------------
__global__ void init_kernel() {
    int i = blockIdx.x * blockDim.x + threadIdx.x;
    if (i < B_ * N_) {
        g_rmax[i] = 0u;
        g_bcnt[i] = 0;
        g_oflow[i] = 0;
    }
    if (i < B_) {
        g_nval[i] = 0; g_ninv[i] = 0; g_nconf[i] = 0; g_contrib[i] = 0.0;
    }
}

__global__ void zero_tiles_kernel() {
    size_t i = (size_t)blockIdx.x * blockDim.x + threadIdx.x;
    size_t total = (size_t)B_ * NT * 4096;
    uint4 z = make_uint4(0u, 0u, 0u, 0u);
    for (; i < total; i += (size_t)gridDim.x * blockDim.x) {
        g_Vt[i] = z;
        g_Rt[i] = z;
    }
}

// ---------------- mask dtype detection ----------------
__global__ void detect_kernel(const unsigned char* __restrict__ mraw) {
    __shared__ int s_f3f, s_foff;
    if (threadIdx.x == 0) { s_f3f = 0; s_foff = 0; }
    __syncthreads();
    int f3f = 0, foff = 0;
    for (int i = threadIdx.x; i < B_ * N_; i += blockDim.x) {
        unsigned char c = mraw[i];
        if ((i & 3) == 3 && c == 0x3f) f3f = 1;
        if ((i & 3) != 0 && c != 0)    foff = 1;
    }
    if (f3f)  atomicOr(&s_f3f, 1);
    if (foff) atomicOr(&s_foff, 1);
    __syncthreads();
    if (threadIdx.x == 0) g_mask_mode = s_f3f ? 2 : (s_foff ? 1 : 0);
}

// ---------------- normalize + compact (one warp per point) ----------------
__global__ void norm_compact_kernel(const float* __restrict__ feat,
                                    const void*  __restrict__ mraw) {
    int gw   = (int)((blockIdx.x * blockDim.x + threadIdx.x) >> 5);
    int lane = threadIdx.x & 31;
    if (gw >= B_ * N_) return;
    int b = gw / N_;

    int mv = 0;
    if (lane == 0) {
        int mode = g_mask_mode;
        if (mode == 0)      mv = (((const int*)mraw)[gw] != 0);
        else if (mode == 1) mv = (((const unsigned char*)mraw)[gw] != 0);
        else                mv = (((const float*)mraw)[gw] != 0.0f);
    }
    mv = __shfl_sync(0xffffffffu, mv, 0);

    const float* src = feat + (size_t)gw * D_;
    float4 v0 = ((const float4*)src)[lane];
    float4 v1 = ((const float4*)src)[lane + 32];
    float ss = v0.x * v0.x + v0.y * v0.y + v0.z * v0.z + v0.w * v0.w
             + v1.x * v1.x + v1.y * v1.y + v1.z * v1.z + v1.w * v1.w;
#pragma unroll
    for (int o = 16; o; o >>= 1) ss += __shfl_xor_sync(0xffffffffu, ss, o);
    float inv = 1.0f / fmaxf(sqrtf(ss), 1e-12f);
    v0.x *= inv; v0.y *= inv; v0.z *= inv; v0.w *= inv;
    v1.x *= inv; v1.y *= inv; v1.z *= inv; v1.w *= inv;

    int slot = 0;
    if (lane == 0)
        slot = atomicAdd(mv ? &g_nval[b] : &g_ninv[b], 1);
    slot = __shfl_sync(0xffffffffu, slot, 0);

    float* df = (mv ? g_Vf : g_Rf) + ((size_t)b * N_ + slot) * D_;
    ((float4*)df)[lane]      = v0;
    ((float4*)df)[lane + 32] = v1;

    char* img = (char*)((mv ? g_Vt : g_Rt)
                + ((size_t)b * NT + (slot >> 7)) * 4096);
    int c = slot & 127;
    __nv_bfloat162 p0 = __floats2bfloat162_rn(v0.x, v0.y);
    __nv_bfloat162 p1 = __floats2bfloat162_rn(v0.z, v0.w);
    uint2 h; h.x = *(uint32_t*)&p0; h.y = *(uint32_t*)&p1;
    uint32_t o0 = sw128(img_off(c, lane >> 1)) + (uint32_t)(lane & 1) * 8u;
    *(uint2*)(img + o0) = h;
    p0 = __floats2bfloat162_rn(v1.x, v1.y);
    p1 = __floats2bfloat162_rn(v1.z, v1.w);
    h.x = *(uint32_t*)&p0; h.y = *(uint32_t*)&p1;
    uint32_t o1 = sw128(img_off(c, 16 + (lane >> 1))) + (uint32_t)(lane & 1) * 8u;
    *(uint2*)(img + o1) = h;
}

// ---------------- pass 1: bulk-copy bf16 HMMA -> row max + candidate bits --
__global__ __launch_bounds__(256, 1) void maxsim_p1() {
    extern __shared__ __align__(1024) char smem[];
    int b = blockIdx.y;
    int ni = g_ninv[b], nv = g_nval[b];
    int row0 = blockIdx.x * 128;
    if (row0 >= ni || nv <= 0) return;

    int tiles_total = (nv + 127) >> 7;
    int tiles_per   = (tiles_total + JSPLIT - 1) / JSPLIT;
    int jt0 = blockIdx.z * tiles_per;
    int jt1 = min(tiles_total, jt0 + tiles_per);
    if (jt0 >= jt1) return;
    int T = jt1 - jt0;

    uint32_t sb = smem_u32_addr(smem);
    uint32_t mbA  = sb + SM_MBAR;
    uint32_t mbB0 = sb + SM_MBAR + 8;
    uint32_t mbB1 = sb + SM_MBAR + 16;
    int tid = threadIdx.x;
    int lane = tid & 31, warp = tid >> 5;
    int warp_m = warp & 1, warp_n = warp >> 1;

    const char* Rt_b = (const char*)(g_Rt + ((size_t)b * NT + (row0 >> 7)) * 4096);
    const char* Vt_b = (const char*)(g_Vt + (size_t)b * NT * 4096);
    unsigned* bm_b = g_bm + (size_t)b * N_ * NW;

    if (tid == 0) {
        MBAR_INIT(mbA, 1);
        MBAR_INIT(mbB0, 1);
        MBAR_INIT(mbB1, 1);
        MBAR_EXPECT_TX(mbA, 65536);
        bulk_ldg(sb + SM_A, Rt_b, 65536, mbA);
        MBAR_EXPECT_TX(mbB0, 65536);
        bulk_ldg(sb + SM_B, Vt_b + (size_t)jt0 * 65536, 65536, mbB0);
    }
    __syncthreads();
    MBAR_WAIT_PARITY(mbA, 0);

    float acc[4][4][4];
#pragma unroll
    for (int mf = 0; mf < 4; ++mf)
#pragma unroll
        for (int nf = 0; nf < 4; ++nf)
#pragma unroll
            for (int q = 0; q < 4; ++q) acc[mf][nf][q] = 0.0f;
    float rm[8];
#pragma unroll
    for (int r = 0; r < 8; ++r) rm[r] = -INFINITY;

    int ph[2] = {0, 0};

    for (int t = 0; t < T; ++t) {
        int sel = t & 1;
        if (t + 1 < T && tid == 0) {
            uint32_t mbn = ((t + 1) & 1) ? mbB1 : mbB0;
            MBAR_EXPECT_TX(mbn, 65536);
            bulk_ldg(sb + SM_B + (uint32_t)((t + 1) & 1) * 65536u,
                     Vt_b + (size_t)(jt0 + t + 1) * 65536, 65536, mbn);
        }
        MBAR_WAIT_PARITY(sel ? mbB1 : mbB0, ph[sel]);
        ph[sel] ^= 1;
        uint32_t bbase = sb + SM_B + (uint32_t)sel * 65536u;

#pragma unroll
        for (int kk = 0; kk < 16; ++kk) {
            int ku = kk * 2 + (lane >> 4);
            uint32_t a[4][4];
#pragma unroll
            for (int mf = 0; mf < 4; ++mf) {
                int row = warp_m * 64 + mf * 16 + (lane & 15);
                ldmatrix_x4(a[mf], sb + SM_A + sw128(img_off(row, ku)));
            }
            uint32_t bf[2][4];
#pragma unroll
            for (int nf2 = 0; nf2 < 2; ++nf2) {
                int col = warp_n * 32 + nf2 * 16 + (lane & 15);
                ldmatrix_x4(bf[nf2], bbase + sw128(img_off(col, ku)));
            }
#pragma unroll
            for (int mf = 0; mf < 4; ++mf)
#pragma unroll
                for (int nf2 = 0; nf2 < 2; ++nf2) {
                    mma16816(acc[mf][nf2 * 2],     a[mf], bf[nf2][0], bf[nf2][2]);
                    mma16816(acc[mf][nf2 * 2 + 1], a[mf], bf[nf2][1], bf[nf2][3]);
                }
        }

        {
            int jt = jt0 + t;
            int wi = (jt * 128 + warp_n * 32) >> 5;
            int shl = 2 * (lane & 3);
#pragma unroll
            for (int mf = 0; mf < 4; ++mf) {
#pragma unroll
                for (int rp = 0; rp < 2; ++rp) {
                    unsigned w = 0u;
                    float mm = -INFINITY;
#pragma unroll
                    for (int nf = 0; nf < 4; ++nf) {
                        float c0 = acc[mf][nf][rp * 2];
                        float c1 = acc[mf][nf][rp * 2 + 1];
                        unsigned bits = (c0 > CAND_T ? 1u : 0u)
                                      | (c1 > CAND_T ? 2u : 0u);
                        w |= bits << (nf * 8 + shl);
                        mm = fmaxf(mm, fmaxf(c0, c1));
                    }
                    w |= __shfl_xor_sync(0xffffffffu, w, 1);
                    w |= __shfl_xor_sync(0xffffffffu, w, 2);
                    int r = row0 + warp_m * 64 + mf * 16 + (lane >> 2) + rp * 8;
                    if ((lane & 3) == 0 && r < ni)
                        bm_b[(size_t)r * NW + wi] = w;
                    rm[mf * 2 + rp] = fmaxf(rm[mf * 2 + rp], mm);
                }
#pragma unroll
                for (int nf = 0; nf < 4; ++nf)
#pragma unroll
                    for (int q = 0; q < 4; ++q) acc[mf][nf][q] = 0.0f;
            }
        }
        __syncthreads();
    }

#pragma unroll
    for (int j = 0; j < 8; ++j) {
        rm[j] = fmaxf(rm[j], __shfl_xor_sync(0xffffffffu, rm[j], 1));
        rm[j] = fmaxf(rm[j], __shfl_xor_sync(0xffffffffu, rm[j], 2));
    }
    float* smax = (float*)(smem + SM_MAX);
    if ((lane & 3) == 0) {
#pragma unroll
        for (int mf = 0; mf < 4; ++mf) {
            int rloc = warp_m * 64 + mf * 16 + (lane >> 2);
            smax[warp_n * 128 + rloc]     = rm[mf * 2];
            smax[warp_n * 128 + rloc + 8] = rm[mf * 2 + 1];
        }
    }
    __syncthreads();
    if (tid < 128) {
        int row = row0 + tid;
        if (row < ni) {
            float m = fmaxf(fmaxf(smax[tid], smax[128 + tid]),
                            fmaxf(smax[256 + tid], smax[384 + tid]));
            atomicMax(&g_rmax[b * N_ + row], enc_max(m));
        }
    }
}

// ---------------- group: bucket gated rows by first candidate col ---------
__global__ void group_kernel() {
    int i = blockIdx.x * blockDim.x + threadIdx.x;
    if (i >= B_ * N_) return;
    int b = i / N_, row = i - b * N_;
    int ni = g_ninv[b], nv = g_nval[b];
    if (row >= ni || nv <= 0) return;
    if (!(dec_max(g_rmax[i]) > SKIP_M)) return;

    const unsigned* bmr = g_bm + (size_t)i * NW;
    int wcap = ((nv + 127) >> 7) * 4;     // words actually written by p1
    int rep = -1;
    for (int w = 0; w < wcap; ++w) {
        unsigned v = bmr[w];
        if (v) { rep = w * 32 + __ffs(v) - 1; break; }
    }
    if (rep < 0) return;
    int slot = atomicAdd(&g_bcnt[b * N_ + rep], 1);
    if (slot < BK_ROWS)
        g_blist[(size_t)(b * N_ + rep) * BK_ROWS + slot] = (unsigned short)row;
    else
        g_oflow[i] = 1;
}

// ---------------- bucket rescore: union cols in SMEM, exact fp32 dots -----
__global__ __launch_bounds__(256) void bucket_rescore() {
    extern __shared__ __align__(16) char bsm[];
    float4*         colbuf = (float4*)bsm;                   // [BK_COLS][64]
    unsigned*       su     = (unsigned*)(bsm + 131072);      // [NW]
    unsigned short* slist  = (unsigned short*)(bsm + 131072 + 1536);
    __shared__ int sc;

    int rep = blockIdx.x, b = blockIdx.y;
    int cnt = g_bcnt[b * N_ + rep];
    if (cnt == 0) return;
    int rows = min(cnt, BK_ROWS);
    int nv = g_nval[b];
    int wcap = ((nv + 127) >> 7) * 4;
    int tid = threadIdx.x;
    const unsigned short* rlist = g_blist + (size_t)(b * N_ + rep) * BK_ROWS;

    for (int w = tid; w < wcap; w += 256) su[w] = 0u;
    if (tid == 0) sc = 0;
    __syncthreads();
    for (int ri = 0; ri < rows; ++ri) {
        const unsigned* bmr = g_bm + ((size_t)b * N_ + rlist[ri]) * NW;
        for (int w = tid; w < wcap; w += 256) su[w] |= bmr[w];
    }
    __syncthreads();
    for (int w = tid; w < wcap; w += 256) {
        unsigned v = su[w];
        while (v) {
            int bit = __ffs(v) - 1;
            v &= v - 1;
            int idx = atomicAdd(&sc, 1);
            if (idx < BK_COLS) slist[idx] = (unsigned short)(w * 32 + bit);
        }
    }
    __syncthreads();
    int ncols = sc;
    if (ncols > BK_COLS) {
        for (int ri = tid; ri < rows; ri += 256)
            g_oflow[b * N_ + rlist[ri]] = 1;
        return;
    }

    const float* vb = g_Vf + (size_t)b * N_ * D_;
    for (int idx = tid; idx < ncols * 64; idx += 256) {
        int c = idx >> 6, e = idx & 63;
        colbuf[c * 64 + e] = ((const float4*)(vb + (size_t)slist[c] * D_))[e];
    }
    __syncthreads();

    int wl = tid >> 5, lane = tid & 31;
    for (int ri = wl; ri < rows; ri += 8) {
        int row = rlist[ri];
        const float4* rf4 = (const float4*)(g_Rf + ((size_t)b * N_ + row) * D_);
        float4 r0 = rf4[lane], r1 = rf4[lane + 32];
        float best = -INFINITY;
        int c = 0;
        for (; c + 4 <= ncols; c += 4) {
            float s[4];
#pragma unroll
            for (int u = 0; u < 4; ++u)
                s[u] = dot8(colbuf[(c + u) * 64 + lane],
                            colbuf[(c + u) * 64 + 32 + lane], r0, r1);
#pragma unroll
            for (int o = 16; o; o >>= 1)
#pragma unroll
                for (int u = 0; u < 4; ++u)
                    s[u] += __shfl_xor_sync(0xffffffffu, s[u], o);
            best = fmaxf(best, fmaxf(fmaxf(s[0], s[1]), fmaxf(s[2], s[3])));
        }
        for (; c < ncols; ++c) {
            float s = dot8(colbuf[c * 64 + lane],
                           colbuf[c * 64 + 32 + lane], r0, r1);
#pragma unroll
            for (int o = 16; o; o >>= 1)
                s += __shfl_xor_sync(0xffffffffu, s, o);
            best = fmaxf(best, s);
        }
        if (lane == 0 && best > CONF_THRESH) {
            atomicAdd(&g_contrib[b], (double)(1.0f - best));
            atomicAdd(&g_nconf[b], 1);
        }
    }
}

// ---------------- fallback rescore (overflow rows only) -------------------
__global__ __launch_bounds__(256) void fallback_rescore() {
    int gw = (int)((blockIdx.x * blockDim.x + threadIdx.x) >> 5);
    int lane = threadIdx.x & 31;
    if (gw >= B_ * N_) return;
    int b = gw / N_, row = gw - b * N_;
    if (!g_oflow[gw]) return;
    int nv = g_nval[b];
    int wcap = ((nv + 127) >> 7) * 4;

    const unsigned* bmr = g_bm + (size_t)gw * NW;
    const float* rf = g_Rf + (size_t)gw * D_;
    float4 r0 = ((const float4*)rf)[lane];
    float4 r1 = ((const float4*)rf)[lane + 32];
    const float* vb = g_Vf + (size_t)b * N_ * D_;

    float best = -INFINITY;
    for (int w = 0; w < wcap; ++w) {
        unsigned v = bmr[w];
        while (v) {
            int bit = __ffs(v) - 1;
            v &= v - 1;
            int col = w * 32 + bit;
            const float4* vc = (const float4*)(vb + (size_t)col * D_);
            float s = dot8(vc[lane], vc[lane + 32], r0, r1);
#pragma unroll
            for (int o = 16; o; o >>= 1)
                s += __shfl_xor_sync(0xffffffffu, s, o);
            best = fmaxf(best, s);
        }
    }
    if (lane == 0 && best > CONF_THRESH) {
        atomicAdd(&g_contrib[b], (double)(1.0f - best));
        atomicAdd(&g_nconf[b], 1);
    }
}

// ---------------- finalize ----------------
__global__ void finalize_kernel(float* out) {
    if (threadIdx.x == 0 && blockIdx.x == 0) {
        double tl = 0.0, tp = 0.0;
        for (int b = 0; b < B_; ++b) {
            int ni = g_ninv[b], nvv = g_nval[b], nc = g_nconf[b];
            bool active = (nc > 0) && (nvv > 0) && (ni > 0);
            if (active) {
                double pseudo = g_contrib[b] / (double)(nc > 1 ? nc : 1);
                tl += pseudo * (double)ni;
                tp += (double)ni;
            }
        }
        out[0] = (tp > 0.0) ? (float)(0.01 * tl / tp) : 0.0f;
    }
}

// ---------------- launch ----------------
extern "C" void kernel_launch(void* const* d_in, const int* in_sizes, int n_in,
                              void* d_out, int out_size) {
    int fi = 0, mi = 1;
    if (n_in >= 2 && in_sizes[0] < in_sizes[1]) { fi = 1; mi = 0; }
    const float* feat = (const float*)d_in[fi];
    const void*  mask = d_in[mi];

    cudaFuncSetAttribute(maxsim_p1, cudaFuncAttributeMaxDynamicSharedMemorySize,
                         SMEM_BYTES);
    cudaFuncSetAttribute(bucket_rescore,
                         cudaFuncAttributeMaxDynamicSharedMemorySize, BSM_BYTES);

    init_kernel<<<(B_ * N_ + 255) / 256, 256>>>();
    zero_tiles_kernel<<<592, 256>>>();
    detect_kernel<<<1, 1024>>>((const unsigned char*)mask);
    norm_compact_kernel<<<(B_ * N_ * 32 + 255) / 256, 256>>>(feat, mask);
    dim3 g(N_ / 128, B_, JSPLIT);
    maxsim_p1<<<g, 256, SMEM_BYTES>>>();
    group_kernel<<<(B_ * N_ + 255) / 256, 256>>>();
    dim3 gb(N_, B_);
    bucket_rescore<<<gb, 256, BSM_BYTES>>>();
    fallback_rescore<<<(B_ * N_ * 32 + 255) / 256, 256>>>();
    finalize_kernel<<<1, 32>>>((float*)d_out);
}

// round 14
// speedup vs baseline: 1.1909x; 1.1909x over previous
#include <cuda_runtime.h>
#include <cuda_bf16.h>
#include <math.h>
#include <stdint.h>

// Problem constants
#define B_ 2
#define N_ 12288
#define D_ 256
#define NW (N_ / 32)            // bitmask words per row = 384
#define NT (N_ / 128)           // 128-wide tiles per batch = 96
#define CONF_THRESH 0.8f
#define JSPLIT 3
// bf16 mma sim abs error bound ~0.0044:
#define CAND_T    0.7925f       // flag threshold (abs)
#define SKIP_M    0.7956f       // row skip: m <= SKIP_M => true max <= 0.8
// bucket-rescore capacities
#define BK_ROWS 256
#define BK_COLS 128

// ---------------- device scratch (no allocations allowed) ----------------
__device__ __align__(128) uint4 g_Vt[(size_t)B_ * NT * 4096];
__device__ __align__(128) uint4 g_Rt[(size_t)B_ * NT * 4096];
__device__ float    g_Vf[(size_t)B_ * N_ * D_];
__device__ float    g_Rf[(size_t)B_ * N_ * D_];
__device__ unsigned g_bm[(size_t)B_ * N_ * NW];   // candidate bitmask
__device__ int      g_bcnt[B_ * N_];              // bucket counts (rep col)
__device__ unsigned short g_blist[(size_t)B_ * N_ * BK_ROWS];
__device__ unsigned char  g_oflow[B_ * N_];       // fallback flags
__device__ int      g_work[B_ * N_];              // bucket worklist
__device__ int      g_nwork;
__device__ int      g_cursor;
__device__ int      g_nval[B_];
__device__ int      g_ninv[B_];
__device__ int      g_nconf[B_];
__device__ unsigned g_rmax[B_ * N_];     // monotonic-encoded approx row max
__device__ double   g_contrib[B_];
__device__ int      g_mask_mode;         // 0=int32, 1=uint8, 2=float32

// SMEM layout (p1, bytes)
#define SM_A    0u
#define SM_B    65536u
#define SM_MAX  196608u
#define SM_MBAR 198656u
#define SMEM_BYTES 198720
// bucket kernel dynamic smem: colbuf 128*1KB + union 1536 + slist 256
#define BSM_BYTES (131072 + 1536 + 256)

// ---------------- small helpers ----------------
__device__ __forceinline__ uint32_t smem_u32_addr(const void* p) {
    uint32_t a;
    asm("{ .reg .u64 t; cvta.to.shared.u64 t, %1; cvt.u32.u64 %0, t; }"
        : "=r"(a) : "l"(p));
    return a;
}
__device__ __forceinline__ uint32_t sw128(uint32_t off) {
    return off ^ ((off >> 3) & 0x70u);
}
__device__ __forceinline__ uint32_t img_off(int c, int ku) {
    return (uint32_t)((c >> 3) * 4 + (ku >> 3)) * 1024u
         + (uint32_t)(c & 7) * 128u + (uint32_t)(ku & 7) * 16u;
}
__device__ __forceinline__ void ldmatrix_x4(uint32_t* r, uint32_t addr) {
    asm volatile("ldmatrix.sync.aligned.m8n8.x4.shared.b16 {%0,%1,%2,%3}, [%4];"
                 : "=r"(r[0]), "=r"(r[1]), "=r"(r[2]), "=r"(r[3]) : "r"(addr));
}
__device__ __forceinline__ void mma16816(float* c, const uint32_t* a,
                                         uint32_t b0, uint32_t b1) {
    asm volatile(
        "mma.sync.aligned.m16n8k16.row.col.f32.bf16.bf16.f32 "
        "{%0,%1,%2,%3}, {%4,%5,%6,%7}, {%8,%9}, {%0,%1,%2,%3};"
        : "+f"(c[0]), "+f"(c[1]), "+f"(c[2]), "+f"(c[3])
        : "r"(a[0]), "r"(a[1]), "r"(a[2]), "r"(a[3]), "r"(b0), "r"(b1));
}
#define MBAR_INIT(mbar, cnt) \
    asm volatile("mbarrier.init.shared.b64 [%0], %1;" \
                 :: "r"(mbar), "r"((uint32_t)(cnt)) : "memory")
#define MBAR_EXPECT_TX(mbar, tx) \
    asm volatile("mbarrier.arrive.expect_tx.shared.b64 _, [%0], %1;" \
                 :: "r"(mbar), "r"((uint32_t)(tx)) : "memory")
__device__ __forceinline__ void bulk_ldg(uint32_t sdst, const void* gsrc,
                                         uint32_t bytes, uint32_t mbar) {
    asm volatile(
        "cp.async.bulk.shared::cluster.global.mbarrier::complete_tx::bytes "
        "[%0], [%1], %2, [%3];"
        :: "r"(sdst), "l"(gsrc), "r"(bytes), "r"(mbar) : "memory");
}
#define MBAR_WAIT_PARITY(mbar, par) do {                                           \
    uint32_t _m = (mbar); uint32_t _p = (uint32_t)(par); uint32_t _d;              \
    asm volatile("{ .reg .pred p; "                                                \
        "mbarrier.try_wait.parity.acquire.cta.shared::cta.b64 p, [%1], %2; "       \
        "selp.b32 %0, 1, 0, p; }" : "=r"(_d) : "r"(_m), "r"(_p) : "memory");       \
    if (!_d) {                                                                     \
        asm volatile("{ .reg .pred P1; "                                           \
            "WL_%=: mbarrier.try_wait.parity.acquire.cta.shared::cta.b64 P1, [%0], %1, 0x989680; " \
            "@P1 bra.uni WD_%=; bra.uni WL_%=; WD_%=: }"                           \
            :: "r"(_m), "r"(_p) : "memory");                                       \
    }                                                                              \
} while (0)
__device__ __forceinline__ unsigned enc_max(float m) {
    int rep = __float_as_int(m);
    return (rep < 0) ? ~((unsigned)rep) : ((unsigned)rep | 0x80000000u);
}
__device__ __forceinline__ float dec_max(unsigned key) {
    return (key & 0x80000000u) ? __uint_as_float(key & 0x7fffffffu)
                               : __uint_as_float(~key);
}
__device__ __forceinline__ float dot8(float4 x0, float4 x1,
                                      float4 r0, float4 r1) {
    float s = 0.0f;
    s = fmaf(x0.x, r0.x, s); s = fmaf(x0.y, r0.y, s);
    s = fmaf(x0.z, r0.z, s); s = fmaf(x0.w, r0.w, s);
    s = fmaf(x1.x, r1.x, s); s = fmaf(x1.y, r1.y, s);
    s = fmaf(x1.z, r1.z, s); s = fmaf(x1.w, r1.w, s);
    return s;
}

// ---------------- init ----------------
__global__ void init_kernel() {
    int i = blockIdx.x * blockDim.x + threadIdx.x;
    if (i < B_ * N_) {
        g_rmax[i] = 0u;
        g_bcnt[i] = 0;
        g_oflow[i] = 0;
    }
    if (i == 0) { g_nwork = 0; g_cursor = 0; }
    if (i < B_) {
        g_nval[i] = 0; g_ninv[i] = 0; g_nconf[i] = 0; g_contrib[i] = 0.0;
    }
}

__global__ void zero_tiles_kernel() {
    size_t i = (size_t)blockIdx.x * blockDim.x + threadIdx.x;
    size_t total = (size_t)B_ * NT * 4096;
    uint4 z = make_uint4(0u, 0u, 0u, 0u);
    for (; i < total; i += (size_t)gridDim.x * blockDim.x) {
        g_Vt[i] = z;
        g_Rt[i] = z;
    }
}

// ---------------- mask dtype detection ----------------
__global__ void detect_kernel(const unsigned char* __restrict__ mraw) {
    __shared__ int s_f3f, s_foff;
    if (threadIdx.x == 0) { s_f3f = 0; s_foff = 0; }
    __syncthreads();
    int f3f = 0, foff = 0;
    for (int i = threadIdx.x; i < B_ * N_; i += blockDim.x) {
        unsigned char c = mraw[i];
        if ((i & 3) == 3 && c == 0x3f) f3f = 1;
        if ((i & 3) != 0 && c != 0)    foff = 1;
    }
    if (f3f)  atomicOr(&s_f3f, 1);
    if (foff) atomicOr(&s_foff, 1);
    __syncthreads();
    if (threadIdx.x == 0) g_mask_mode = s_f3f ? 2 : (s_foff ? 1 : 0);
}

// ---------------- normalize + compact (one warp per point) ----------------
__global__ void norm_compact_kernel(const float* __restrict__ feat,
                                    const void*  __restrict__ mraw) {
    int gw   = (int)((blockIdx.x * blockDim.x + threadIdx.x) >> 5);
    int lane = threadIdx.x & 31;
    if (gw >= B_ * N_) return;
    int b = gw / N_;

    int mv = 0;
    if (lane == 0) {
        int mode = g_mask_mode;
        if (mode == 0)      mv = (((const int*)mraw)[gw] != 0);
        else if (mode == 1) mv = (((const unsigned char*)mraw)[gw] != 0);
        else                mv = (((const float*)mraw)[gw] != 0.0f);
    }
    mv = __shfl_sync(0xffffffffu, mv, 0);

    const float* src = feat + (size_t)gw * D_;
    float4 v0 = ((const float4*)src)[lane];
    float4 v1 = ((const float4*)src)[lane + 32];
    float ss = v0.x * v0.x + v0.y * v0.y + v0.z * v0.z + v0.w * v0.w
             + v1.x * v1.x + v1.y * v1.y + v1.z * v1.z + v1.w * v1.w;
#pragma unroll
    for (int o = 16; o; o >>= 1) ss += __shfl_xor_sync(0xffffffffu, ss, o);
    float inv = 1.0f / fmaxf(sqrtf(ss), 1e-12f);
    v0.x *= inv; v0.y *= inv; v0.z *= inv; v0.w *= inv;
    v1.x *= inv; v1.y *= inv; v1.z *= inv; v1.w *= inv;

    int slot = 0;
    if (lane == 0)
        slot = atomicAdd(mv ? &g_nval[b] : &g_ninv[b], 1);
    slot = __shfl_sync(0xffffffffu, slot, 0);

    float* df = (mv ? g_Vf : g_Rf) + ((size_t)b * N_ + slot) * D_;
    ((float4*)df)[lane]      = v0;
    ((float4*)df)[lane + 32] = v1;

    char* img = (char*)((mv ? g_Vt : g_Rt)
                + ((size_t)b * NT + (slot >> 7)) * 4096);
    int c = slot & 127;
    __nv_bfloat162 p0 = __floats2bfloat162_rn(v0.x, v0.y);
    __nv_bfloat162 p1 = __floats2bfloat162_rn(v0.z, v0.w);
    uint2 h; h.x = *(uint32_t*)&p0; h.y = *(uint32_t*)&p1;
    uint32_t o0 = sw128(img_off(c, lane >> 1)) + (uint32_t)(lane & 1) * 8u;
    *(uint2*)(img + o0) = h;
    p0 = __floats2bfloat162_rn(v1.x, v1.y);
    p1 = __floats2bfloat162_rn(v1.z, v1.w);
    h.x = *(uint32_t*)&p0; h.y = *(uint32_t*)&p1;
    uint32_t o1 = sw128(img_off(c, 16 + (lane >> 1))) + (uint32_t)(lane & 1) * 8u;
    *(uint2*)(img + o1) = h;
}

// ---------------- pass 1: bulk-copy bf16 HMMA -> row max + candidate bits --
__global__ __launch_bounds__(256, 1) void maxsim_p1() {
    extern __shared__ __align__(1024) char smem[];
    int b = blockIdx.y;
    int ni = g_ninv[b], nv = g_nval[b];
    int row0 = blockIdx.x * 128;
    if (row0 >= ni || nv <= 0) return;

    int tiles_total = (nv + 127) >> 7;
    int tiles_per   = (tiles_total + JSPLIT - 1) / JSPLIT;
    int jt0 = blockIdx.z * tiles_per;
    int jt1 = min(tiles_total, jt0 + tiles_per);
    if (jt0 >= jt1) return;
    int T = jt1 - jt0;

    uint32_t sb = smem_u32_addr(smem);
    uint32_t mbA  = sb + SM_MBAR;
    uint32_t mbB0 = sb + SM_MBAR + 8;
    uint32_t mbB1 = sb + SM_MBAR + 16;
    int tid = threadIdx.x;
    int lane = tid & 31, warp = tid >> 5;
    int warp_m = warp & 1, warp_n = warp >> 1;

    const char* Rt_b = (const char*)(g_Rt + ((size_t)b * NT + (row0 >> 7)) * 4096);
    const char* Vt_b = (const char*)(g_Vt + (size_t)b * NT * 4096);
    unsigned* bm_b = g_bm + (size_t)b * N_ * NW;

    if (tid == 0) {
        MBAR_INIT(mbA, 1);
        MBAR_INIT(mbB0, 1);
        MBAR_INIT(mbB1, 1);
        MBAR_EXPECT_TX(mbA, 65536);
        bulk_ldg(sb + SM_A, Rt_b, 65536, mbA);
        MBAR_EXPECT_TX(mbB0, 65536);
        bulk_ldg(sb + SM_B, Vt_b + (size_t)jt0 * 65536, 65536, mbB0);
    }
    __syncthreads();
    MBAR_WAIT_PARITY(mbA, 0);

    float acc[4][4][4];
#pragma unroll
    for (int mf = 0; mf < 4; ++mf)
#pragma unroll
        for (int nf = 0; nf < 4; ++nf)
#pragma unroll
            for (int q = 0; q < 4; ++q) acc[mf][nf][q] = 0.0f;
    float rm[8];
#pragma unroll
    for (int r = 0; r < 8; ++r) rm[r] = -INFINITY;

    int ph[2] = {0, 0};

    for (int t = 0; t < T; ++t) {
        int sel = t & 1;
        if (t + 1 < T && tid == 0) {
            uint32_t mbn = ((t + 1) & 1) ? mbB1 : mbB0;
            MBAR_EXPECT_TX(mbn, 65536);
            bulk_ldg(sb + SM_B + (uint32_t)((t + 1) & 1) * 65536u,
                     Vt_b + (size_t)(jt0 + t + 1) * 65536, 65536, mbn);
        }
        MBAR_WAIT_PARITY(sel ? mbB1 : mbB0, ph[sel]);
        ph[sel] ^= 1;
        uint32_t bbase = sb + SM_B + (uint32_t)sel * 65536u;

#pragma unroll
        for (int kk = 0; kk < 16; ++kk) {
            int ku = kk * 2 + (lane >> 4);
            uint32_t a[4][4];
#pragma unroll
            for (int mf = 0; mf < 4; ++mf) {
                int row = warp_m * 64 + mf * 16 + (lane & 15);
                ldmatrix_x4(a[mf], sb + SM_A + sw128(img_off(row, ku)));
            }
            uint32_t bf[2][4];
#pragma unroll
            for (int nf2 = 0; nf2 < 2; ++nf2) {
                int col = warp_n * 32 + nf2 * 16 + (lane & 15);
                ldmatrix_x4(bf[nf2], bbase + sw128(img_off(col, ku)));
            }
#pragma unroll
            for (int mf = 0; mf < 4; ++mf)
#pragma unroll
                for (int nf2 = 0; nf2 < 2; ++nf2) {
                    mma16816(acc[mf][nf2 * 2],     a[mf], bf[nf2][0], bf[nf2][2]);
                    mma16816(acc[mf][nf2 * 2 + 1], a[mf], bf[nf2][1], bf[nf2][3]);
                }
        }

        {
            int jt = jt0 + t;
            int wi = (jt * 128 + warp_n * 32) >> 5;
            int shl = 2 * (lane & 3);
#pragma unroll
            for (int mf = 0; mf < 4; ++mf) {
#pragma unroll
                for (int rp = 0; rp < 2; ++rp) {
                    unsigned w = 0u;
                    float mm = -INFINITY;
#pragma unroll
                    for (int nf = 0; nf < 4; ++nf) {
                        float c0 = acc[mf][nf][rp * 2];
                        float c1 = acc[mf][nf][rp * 2 + 1];
                        unsigned bits = (c0 > CAND_T ? 1u : 0u)
                                      | (c1 > CAND_T ? 2u : 0u);
                        w |= bits << (nf * 8 + shl);
                        mm = fmaxf(mm, fmaxf(c0, c1));
                    }
                    w |= __shfl_xor_sync(0xffffffffu, w, 1);
                    w |= __shfl_xor_sync(0xffffffffu, w, 2);
                    int r = row0 + warp_m * 64 + mf * 16 + (lane >> 2) + rp * 8;
                    if ((lane & 3) == 0 && r < ni)
                        bm_b[(size_t)r * NW + wi] = w;
                    rm[mf * 2 + rp] = fmaxf(rm[mf * 2 + rp], mm);
                }
#pragma unroll
                for (int nf = 0; nf < 4; ++nf)
#pragma unroll
                    for (int q = 0; q < 4; ++q) acc[mf][nf][q] = 0.0f;
            }
        }
        __syncthreads();
    }

#pragma unroll
    for (int j = 0; j < 8; ++j) {
        rm[j] = fmaxf(rm[j], __shfl_xor_sync(0xffffffffu, rm[j], 1));
        rm[j] = fmaxf(rm[j], __shfl_xor_sync(0xffffffffu, rm[j], 2));
    }
    float* smax = (float*)(smem + SM_MAX);
    if ((lane & 3) == 0) {
#pragma unroll
        for (int mf = 0; mf < 4; ++mf) {
            int rloc = warp_m * 64 + mf * 16 + (lane >> 2);
            smax[warp_n * 128 + rloc]     = rm[mf * 2];
            smax[warp_n * 128 + rloc + 8] = rm[mf * 2 + 1];
        }
    }
    __syncthreads();
    if (tid < 128) {
        int row = row0 + tid;
        if (row < ni) {
            float m = fmaxf(fmaxf(smax[tid], smax[128 + tid]),
                            fmaxf(smax[256 + tid], smax[384 + tid]));
            atomicMax(&g_rmax[b * N_ + row], enc_max(m));
        }
    }
}

// ---------------- group: bucket gated rows by first candidate col ---------
__global__ void group_kernel() {
    int i = blockIdx.x * blockDim.x + threadIdx.x;
    if (i >= B_ * N_) return;
    int b = i / N_, row = i - b * N_;
    int ni = g_ninv[b], nv = g_nval[b];
    if (row >= ni || nv <= 0) return;
    if (!(dec_max(g_rmax[i]) > SKIP_M)) return;

    const unsigned* bmr = g_bm + (size_t)i * NW;
    int wcap = ((nv + 127) >> 7) * 4;
    int rep = -1;
    for (int w = 0; w < wcap; ++w) {
        unsigned v = bmr[w];
        if (v) { rep = w * 32 + __ffs(v) - 1; break; }
    }
    if (rep < 0) return;
    int slot = atomicAdd(&g_bcnt[b * N_ + rep], 1);
    if (slot < BK_ROWS)
        g_blist[(size_t)(b * N_ + rep) * BK_ROWS + slot] = (unsigned short)row;
    else
        g_oflow[i] = 1;
}

// ---------------- build bucket worklist ----------------
__global__ void buildwork_kernel() {
    int i = blockIdx.x * blockDim.x + threadIdx.x;
    if (i >= B_ * N_) return;
    if (g_bcnt[i] > 0) {
        int w = atomicAdd(&g_nwork, 1);
        g_work[w] = i;
    }
}

// ---------------- bucket rescore: persistent CTAs over the worklist --------
__global__ __launch_bounds__(256) void bucket_rescore() {
    extern __shared__ __align__(16) char bsm[];
    float4*         colbuf = (float4*)bsm;                   // [BK_COLS][64]
    unsigned*       su     = (unsigned*)(bsm + 131072);      // [NW]
    unsigned short* slist  = (unsigned short*)(bsm + 131072 + 1536);
    __shared__ int sc;
    __shared__ int sjob;

    int tid = threadIdx.x;

    for (;;) {
        if (tid == 0) sjob = atomicAdd(&g_cursor, 1);
        __syncthreads();
        int job = sjob;
        if (job >= g_nwork) return;
        int bucket = g_work[job];
        int b = bucket / N_;
        int cnt = g_bcnt[bucket];
        int rows = min(cnt, BK_ROWS);
        int nv = g_nval[b];
        int wcap = ((nv + 127) >> 7) * 4;
        const unsigned short* rlist = g_blist + (size_t)bucket * BK_ROWS;

        for (int w = tid; w < wcap; w += 256) su[w] = 0u;
        if (tid == 0) sc = 0;
        __syncthreads();
        for (int ri = 0; ri < rows; ++ri) {
            const unsigned* bmr = g_bm + ((size_t)b * N_ + rlist[ri]) * NW;
            for (int w = tid; w < wcap; w += 256) su[w] |= bmr[w];
        }
        __syncthreads();
        for (int w = tid; w < wcap; w += 256) {
            unsigned v = su[w];
            while (v) {
                int bit = __ffs(v) - 1;
                v &= v - 1;
                int idx = atomicAdd(&sc, 1);
                if (idx < BK_COLS) slist[idx] = (unsigned short)(w * 32 + bit);
            }
        }
        __syncthreads();
        int ncols = sc;
        if (ncols > BK_COLS) {
            for (int ri = tid; ri < rows; ri += 256)
                g_oflow[b * N_ + rlist[ri]] = 1;
            __syncthreads();
            continue;
        }

        const float* vb = g_Vf + (size_t)b * N_ * D_;
        for (int idx = tid; idx < ncols * 64; idx += 256) {
            int c = idx >> 6, e = idx & 63;
            colbuf[c * 64 + e] = ((const float4*)(vb + (size_t)slist[c] * D_))[e];
        }
        __syncthreads();

        int wl = tid >> 5, lane = tid & 31;
        for (int ri = wl; ri < rows; ri += 8) {
            int row = rlist[ri];
            const float4* rf4 = (const float4*)(g_Rf + ((size_t)b * N_ + row) * D_);
            float4 r0 = rf4[lane], r1 = rf4[lane + 32];
            float best = -INFINITY;
            int c = 0;
            for (; c + 4 <= ncols; c += 4) {
                float s[4];
#pragma unroll
                for (int u = 0; u < 4; ++u)
                    s[u] = dot8(colbuf[(c + u) * 64 + lane],
                                colbuf[(c + u) * 64 + 32 + lane], r0, r1);
#pragma unroll
                for (int o = 16; o; o >>= 1)
#pragma unroll
                    for (int u = 0; u < 4; ++u)
                        s[u] += __shfl_xor_sync(0xffffffffu, s[u], o);
                best = fmaxf(best, fmaxf(fmaxf(s[0], s[1]), fmaxf(s[2], s[3])));
            }
            for (; c < ncols; ++c) {
                float s = dot8(colbuf[c * 64 + lane],
                               colbuf[c * 64 + 32 + lane], r0, r1);
#pragma unroll
                for (int o = 16; o; o >>= 1)
                    s += __shfl_xor_sync(0xffffffffu, s, o);
                best = fmaxf(best, s);
            }
            if (lane == 0 && best > CONF_THRESH) {
                atomicAdd(&g_contrib[b], (double)(1.0f - best));
                atomicAdd(&g_nconf[b], 1);
            }
        }
        __syncthreads();
    }
}

// ---------------- fallback rescore (overflow rows only) -------------------
__global__ __launch_bounds__(256) void fallback_rescore() {
    int gw = (int)((blockIdx.x * blockDim.x + threadIdx.x) >> 5);
    int lane = threadIdx.x & 31;
    if (gw >= B_ * N_) return;
    int b = gw / N_, row = gw - b * N_;
    if (!g_oflow[gw]) return;
    int nv = g_nval[b];
    int wcap = ((nv + 127) >> 7) * 4;

    const unsigned* bmr = g_bm + (size_t)gw * NW;
    const float* rf = g_Rf + (size_t)gw * D_;
    float4 r0 = ((const float4*)rf)[lane];
    float4 r1 = ((const float4*)rf)[lane + 32];
    const float* vb = g_Vf + (size_t)b * N_ * D_;

    float best = -INFINITY;
    for (int w = 0; w < wcap; ++w) {
        unsigned v = bmr[w];
        while (v) {
            int bit = __ffs(v) - 1;
            v &= v - 1;
            int col = w * 32 + bit;
            const float4* vc = (const float4*)(vb + (size_t)col * D_);
            float s = dot8(vc[lane], vc[lane + 32], r0, r1);
#pragma unroll
            for (int o = 16; o; o >>= 1)
                s += __shfl_xor_sync(0xffffffffu, s, o);
            best = fmaxf(best, s);
        }
    }
    if (lane == 0 && best > CONF_THRESH) {
        atomicAdd(&g_contrib[b], (double)(1.0f - best));
        atomicAdd(&g_nconf[b], 1);
    }
}

// ---------------- finalize ----------------
__global__ void finalize_kernel(float* out) {
    if (threadIdx.x == 0 && blockIdx.x == 0) {
        double tl = 0.0, tp = 0.0;
        for (int b = 0; b < B_; ++b) {
            int ni = g_ninv[b], nvv = g_nval[b], nc = g_nconf[b];
            bool active = (nc > 0) && (nvv > 0) && (ni > 0);
            if (active) {
                double pseudo = g_contrib[b] / (double)(nc > 1 ? nc : 1);
                tl += pseudo * (double)ni;
                tp += (double)ni;
            }
        }
        out[0] = (tp > 0.0) ? (float)(0.01 * tl / tp) : 0.0f;
    }
}

// ---------------- launch ----------------
extern "C" void kernel_launch(void* const* d_in, const int* in_sizes, int n_in,
                              void* d_out, int out_size) {
    int fi = 0, mi = 1;
    if (n_in >= 2 && in_sizes[0] < in_sizes[1]) { fi = 1; mi = 0; }
    const float* feat = (const float*)d_in[fi];
    const void*  mask = d_in[mi];

    cudaFuncSetAttribute(maxsim_p1, cudaFuncAttributeMaxDynamicSharedMemorySize,
                         SMEM_BYTES);
    cudaFuncSetAttribute(bucket_rescore,
                         cudaFuncAttributeMaxDynamicSharedMemorySize, BSM_BYTES);

    init_kernel<<<(B_ * N_ + 255) / 256, 256>>>();
    zero_tiles_kernel<<<592, 256>>>();
    detect_kernel<<<1, 1024>>>((const unsigned char*)mask);
    norm_compact_kernel<<<(B_ * N_ * 32 + 255) / 256, 256>>>(feat, mask);
    dim3 g(N_ / 128, B_, JSPLIT);
    maxsim_p1<<<g, 256, SMEM_BYTES>>>();
    group_kernel<<<(B_ * N_ + 255) / 256, 256>>>();
    buildwork_kernel<<<(B_ * N_ + 255) / 256, 256>>>();
    bucket_rescore<<<148, 256, BSM_BYTES>>>();
    fallback_rescore<<<(B_ * N_ * 32 + 255) / 256, 256>>>();
    finalize_kernel<<<1, 32>>>((float*)d_out);
}

// round 15
// speedup vs baseline: 1.9937x; 1.6741x over previous
#include <cuda_runtime.h>
#include <cuda_bf16.h>
#include <math.h>
#include <stdint.h>

// Problem constants
#define B_ 2
#define N_ 12288
#define D_ 256
#define NW (N_ / 32)            // bitmask words per row = 384
#define NT (N_ / 128)           // 128-wide tiles per batch = 96
#define CONF_THRESH 0.8f
#define JSPLIT 3
// bf16 mma sim abs error bound ~0.0044:
#define CAND_T    0.7925f       // flag threshold (abs)
#define SKIP_M    0.7956f       // row skip: m <= SKIP_M => true max <= 0.8

// ---------------- device scratch (no allocations allowed) ----------------
__device__ __align__(128) uint4 g_Vt[(size_t)B_ * NT * 4096];
__device__ __align__(128) uint4 g_Rt[(size_t)B_ * NT * 4096];
__device__ float    g_Vf[(size_t)B_ * N_ * D_];
__device__ float    g_Rf[(size_t)B_ * N_ * D_];
__device__ unsigned g_bm[(size_t)B_ * N_ * NW];   // candidate bitmask
__device__ int      g_nval[B_];
__device__ int      g_ninv[B_];
__device__ int      g_nconf[B_];
__device__ unsigned g_rmax[B_ * N_];     // monotonic-encoded approx row max
__device__ double   g_contrib[B_];
__device__ int      g_mask_mode;         // 0=int32, 1=uint8, 2=float32

// SMEM layout (p1, bytes)
#define SM_A    0u
#define SM_B    65536u
#define SM_MAX  196608u
#define SM_MBAR 198656u
#define SMEM_BYTES 198720

// ---------------- small helpers ----------------
__device__ __forceinline__ uint32_t smem_u32_addr(const void* p) {
    uint32_t a;
    asm("{ .reg .u64 t; cvta.to.shared.u64 t, %1; cvt.u32.u64 %0, t; }"
        : "=r"(a) : "l"(p));
    return a;
}
__device__ __forceinline__ uint32_t sw128(uint32_t off) {
    return off ^ ((off >> 3) & 0x70u);
}
__device__ __forceinline__ uint32_t img_off(int c, int ku) {
    return (uint32_t)((c >> 3) * 4 + (ku >> 3)) * 1024u
         + (uint32_t)(c & 7) * 128u + (uint32_t)(ku & 7) * 16u;
}
__device__ __forceinline__ void ldmatrix_x4(uint32_t* r, uint32_t addr) {
    asm volatile("ldmatrix.sync.aligned.m8n8.x4.shared.b16 {%0,%1,%2,%3}, [%4];"
                 : "=r"(r[0]), "=r"(r[1]), "=r"(r[2]), "=r"(r[3]) : "r"(addr));
}
__device__ __forceinline__ void mma16816(float* c, const uint32_t* a,
                                         uint32_t b0, uint32_t b1) {
    asm volatile(
        "mma.sync.aligned.m16n8k16.row.col.f32.bf16.bf16.f32 "
        "{%0,%1,%2,%3}, {%4,%5,%6,%7}, {%8,%9}, {%0,%1,%2,%3};"
        : "+f"(c[0]), "+f"(c[1]), "+f"(c[2]), "+f"(c[3])
        : "r"(a[0]), "r"(a[1]), "r"(a[2]), "r"(a[3]), "r"(b0), "r"(b1));
}
#define MBAR_INIT(mbar, cnt) \
    asm volatile("mbarrier.init.shared.b64 [%0], %1;" \
                 :: "r"(mbar), "r"((uint32_t)(cnt)) : "memory")
#define MBAR_EXPECT_TX(mbar, tx) \
    asm volatile("mbarrier.arrive.expect_tx.shared.b64 _, [%0], %1;" \
                 :: "r"(mbar), "r"((uint32_t)(tx)) : "memory")
__device__ __forceinline__ void bulk_ldg(uint32_t sdst, const void* gsrc,
                                         uint32_t bytes, uint32_t mbar) {
    asm volatile(
        "cp.async.bulk.shared::cluster.global.mbarrier::complete_tx::bytes "
        "[%0], [%1], %2, [%3];"
        :: "r"(sdst), "l"(gsrc), "r"(bytes), "r"(mbar) : "memory");
}
#define MBAR_WAIT_PARITY(mbar, par) do {                                           \
    uint32_t _m = (mbar); uint32_t _p = (uint32_t)(par); uint32_t _d;              \
    asm volatile("{ .reg .pred p; "                                                \
        "mbarrier.try_wait.parity.acquire.cta.shared::cta.b64 p, [%1], %2; "       \
        "selp.b32 %0, 1, 0, p; }" : "=r"(_d) : "r"(_m), "r"(_p) : "memory");       \
    if (!_d) {                                                                     \
        asm volatile("{ .reg .pred P1; "                                           \
            "WL_%=: mbarrier.try_wait.parity.acquire.cta.shared::cta.b64 P1, [%0], %1, 0x989680; " \
            "@P1 bra.uni WD_%=; bra.uni WL_%=; WD_%=: }"                           \
            :: "r"(_m), "r"(_p) : "memory");                                       \
    }                                                                              \
} while (0)
__device__ __forceinline__ unsigned enc_max(float m) {
    int rep = __float_as_int(m);
    return (rep < 0) ? ~((unsigned)rep) : ((unsigned)rep | 0x80000000u);
}
__device__ __forceinline__ float dec_max(unsigned key) {
    return (key & 0x80000000u) ? __uint_as_float(key & 0x7fffffffu)
                               : __uint_as_float(~key);
}
__device__ __forceinline__ float dot8(float4 x0, float4 x1,
                                      float4 r0, float4 r1) {
    float s = 0.0f;
    s = fmaf(x0.x, r0.x, s); s = fmaf(x0.y, r0.y, s);
    s = fmaf(x0.z, r0.z, s); s = fmaf(x0.w, r0.w, s);
    s = fmaf(x1.x, r1.x, s); s = fmaf(x1.y, r1.y, s);
    s = fmaf(x1.z, r1.z, s); s = fmaf(x1.w, r1.w, s);
    return s;
}

// ---------------- init ----------------
__global__ void init_kernel() {
    int i = blockIdx.x * blockDim.x + threadIdx.x;
    if (i < B_ * N_) g_rmax[i] = 0u;
    if (i < B_) {
        g_nval[i] = 0; g_ninv[i] = 0; g_nconf[i] = 0; g_contrib[i] = 0.0;
    }
}

__global__ void zero_tiles_kernel() {
    size_t i = (size_t)blockIdx.x * blockDim.x + threadIdx.x;
    size_t total = (size_t)B_ * NT * 4096;
    uint4 z = make_uint4(0u, 0u, 0u, 0u);
    for (; i < total; i += (size_t)gridDim.x * blockDim.x) {
        g_Vt[i] = z;
        g_Rt[i] = z;
    }
}

// ---------------- mask dtype detection ----------------
__global__ void detect_kernel(const unsigned char* __restrict__ mraw) {
    __shared__ int s_f3f, s_foff;
    if (threadIdx.x == 0) { s_f3f = 0; s_foff = 0; }
    __syncthreads();
    int f3f = 0, foff = 0;
    for (int i = threadIdx.x; i < B_ * N_; i += blockDim.x) {
        unsigned char c = mraw[i];
        if ((i & 3) == 3 && c == 0x3f) f3f = 1;
        if ((i & 3) != 0 && c != 0)    foff = 1;
    }
    if (f3f)  atomicOr(&s_f3f, 1);
    if (foff) atomicOr(&s_foff, 1);
    __syncthreads();
    if (threadIdx.x == 0) g_mask_mode = s_f3f ? 2 : (s_foff ? 1 : 0);
}

// ---------------- normalize + compact (one warp per point) ----------------
__global__ void norm_compact_kernel(const float* __restrict__ feat,
                                    const void*  __restrict__ mraw) {
    int gw   = (int)((blockIdx.x * blockDim.x + threadIdx.x) >> 5);
    int lane = threadIdx.x & 31;
    if (gw >= B_ * N_) return;
    int b = gw / N_;

    int mv = 0;
    if (lane == 0) {
        int mode = g_mask_mode;
        if (mode == 0)      mv = (((const int*)mraw)[gw] != 0);
        else if (mode == 1) mv = (((const unsigned char*)mraw)[gw] != 0);
        else                mv = (((const float*)mraw)[gw] != 0.0f);
    }
    mv = __shfl_sync(0xffffffffu, mv, 0);

    const float* src = feat + (size_t)gw * D_;
    float4 v0 = ((const float4*)src)[lane];
    float4 v1 = ((const float4*)src)[lane + 32];
    float ss = v0.x * v0.x + v0.y * v0.y + v0.z * v0.z + v0.w * v0.w
             + v1.x * v1.x + v1.y * v1.y + v1.z * v1.z + v1.w * v1.w;
#pragma unroll
    for (int o = 16; o; o >>= 1) ss += __shfl_xor_sync(0xffffffffu, ss, o);
    float inv = 1.0f / fmaxf(sqrtf(ss), 1e-12f);
    v0.x *= inv; v0.y *= inv; v0.z *= inv; v0.w *= inv;
    v1.x *= inv; v1.y *= inv; v1.z *= inv; v1.w *= inv;

    int slot = 0;
    if (lane == 0)
        slot = atomicAdd(mv ? &g_nval[b] : &g_ninv[b], 1);
    slot = __shfl_sync(0xffffffffu, slot, 0);

    float* df = (mv ? g_Vf : g_Rf) + ((size_t)b * N_ + slot) * D_;
    ((float4*)df)[lane]      = v0;
    ((float4*)df)[lane + 32] = v1;

    char* img = (char*)((mv ? g_Vt : g_Rt)
                + ((size_t)b * NT + (slot >> 7)) * 4096);
    int c = slot & 127;
    __nv_bfloat162 p0 = __floats2bfloat162_rn(v0.x, v0.y);
    __nv_bfloat162 p1 = __floats2bfloat162_rn(v0.z, v0.w);
    uint2 h; h.x = *(uint32_t*)&p0; h.y = *(uint32_t*)&p1;
    uint32_t o0 = sw128(img_off(c, lane >> 1)) + (uint32_t)(lane & 1) * 8u;
    *(uint2*)(img + o0) = h;
    p0 = __floats2bfloat162_rn(v1.x, v1.y);
    p1 = __floats2bfloat162_rn(v1.z, v1.w);
    h.x = *(uint32_t*)&p0; h.y = *(uint32_t*)&p1;
    uint32_t o1 = sw128(img_off(c, 16 + (lane >> 1))) + (uint32_t)(lane & 1) * 8u;
    *(uint2*)(img + o1) = h;
}

// ---------------- pass 1: bulk-copy bf16 HMMA -> row max + candidate bits --
__global__ __launch_bounds__(256, 1) void maxsim_p1() {
    extern __shared__ __align__(1024) char smem[];
    int b = blockIdx.y;
    int ni = g_ninv[b], nv = g_nval[b];
    int row0 = blockIdx.x * 128;
    if (row0 >= ni || nv <= 0) return;

    int tiles_total = (nv + 127) >> 7;
    int tiles_per   = (tiles_total + JSPLIT - 1) / JSPLIT;
    int jt0 = blockIdx.z * tiles_per;
    int jt1 = min(tiles_total, jt0 + tiles_per);
    if (jt0 >= jt1) return;
    int T = jt1 - jt0;

    uint32_t sb = smem_u32_addr(smem);
    uint32_t mbA  = sb + SM_MBAR;
    uint32_t mbB0 = sb + SM_MBAR + 8;
    uint32_t mbB1 = sb + SM_MBAR + 16;
    int tid = threadIdx.x;
    int lane = tid & 31, warp = tid >> 5;
    int warp_m = warp & 1, warp_n = warp >> 1;

    const char* Rt_b = (const char*)(g_Rt + ((size_t)b * NT + (row0 >> 7)) * 4096);
    const char* Vt_b = (const char*)(g_Vt + (size_t)b * NT * 4096);
    unsigned* bm_b = g_bm + (size_t)b * N_ * NW;

    if (tid == 0) {
        MBAR_INIT(mbA, 1);
        MBAR_INIT(mbB0, 1);
        MBAR_INIT(mbB1, 1);
        MBAR_EXPECT_TX(mbA, 65536);
        bulk_ldg(sb + SM_A, Rt_b, 65536, mbA);
        MBAR_EXPECT_TX(mbB0, 65536);
        bulk_ldg(sb + SM_B, Vt_b + (size_t)jt0 * 65536, 65536, mbB0);
    }
    __syncthreads();
    MBAR_WAIT_PARITY(mbA, 0);

    float acc[4][4][4];
#pragma unroll
    for (int mf = 0; mf < 4; ++mf)
#pragma unroll
        for (int nf = 0; nf < 4; ++nf)
#pragma unroll
            for (int q = 0; q < 4; ++q) acc[mf][nf][q] = 0.0f;
    float rm[8];
#pragma unroll
    for (int r = 0; r < 8; ++r) rm[r] = -INFINITY;

    int ph[2] = {0, 0};

    for (int t = 0; t < T; ++t) {
        int sel = t & 1;
        if (t + 1 < T && tid == 0) {
            uint32_t mbn = ((t + 1) & 1) ? mbB1 : mbB0;
            MBAR_EXPECT_TX(mbn, 65536);
            bulk_ldg(sb + SM_B + (uint32_t)((t + 1) & 1) * 65536u,
                     Vt_b + (size_t)(jt0 + t + 1) * 65536, 65536, mbn);
        }
        MBAR_WAIT_PARITY(sel ? mbB1 : mbB0, ph[sel]);
        ph[sel] ^= 1;
        uint32_t bbase = sb + SM_B + (uint32_t)sel * 65536u;

#pragma unroll
        for (int kk = 0; kk < 16; ++kk) {
            int ku = kk * 2 + (lane >> 4);
            uint32_t a[4][4];
#pragma unroll
            for (int mf = 0; mf < 4; ++mf) {
                int row = warp_m * 64 + mf * 16 + (lane & 15);
                ldmatrix_x4(a[mf], sb + SM_A + sw128(img_off(row, ku)));
            }
            uint32_t bf[2][4];
#pragma unroll
            for (int nf2 = 0; nf2 < 2; ++nf2) {
                int col = warp_n * 32 + nf2 * 16 + (lane & 15);
                ldmatrix_x4(bf[nf2], bbase + sw128(img_off(col, ku)));
            }
#pragma unroll
            for (int mf = 0; mf < 4; ++mf)
#pragma unroll
                for (int nf2 = 0; nf2 < 2; ++nf2) {
                    mma16816(acc[mf][nf2 * 2],     a[mf], bf[nf2][0], bf[nf2][2]);
                    mma16816(acc[mf][nf2 * 2 + 1], a[mf], bf[nf2][1], bf[nf2][3]);
                }
        }

        {
            int jt = jt0 + t;
            int wi = (jt * 128 + warp_n * 32) >> 5;
            int shl = 2 * (lane & 3);
#pragma unroll
            for (int mf = 0; mf < 4; ++mf) {
#pragma unroll
                for (int rp = 0; rp < 2; ++rp) {
                    unsigned w = 0u;
                    float mm = -INFINITY;
#pragma unroll
                    for (int nf = 0; nf < 4; ++nf) {
                        float c0 = acc[mf][nf][rp * 2];
                        float c1 = acc[mf][nf][rp * 2 + 1];
                        unsigned bits = (c0 > CAND_T ? 1u : 0u)
                                      | (c1 > CAND_T ? 2u : 0u);
                        w |= bits << (nf * 8 + shl);
                        mm = fmaxf(mm, fmaxf(c0, c1));
                    }
                    w |= __shfl_xor_sync(0xffffffffu, w, 1);
                    w |= __shfl_xor_sync(0xffffffffu, w, 2);
                    int r = row0 + warp_m * 64 + mf * 16 + (lane >> 2) + rp * 8;
                    if ((lane & 3) == 0 && r < ni)
                        bm_b[(size_t)r * NW + wi] = w;
                    rm[mf * 2 + rp] = fmaxf(rm[mf * 2 + rp], mm);
                }
#pragma unroll
                for (int nf = 0; nf < 4; ++nf)
#pragma unroll
                    for (int q = 0; q < 4; ++q) acc[mf][nf][q] = 0.0f;
            }
        }
        __syncthreads();
    }

#pragma unroll
    for (int j = 0; j < 8; ++j) {
        rm[j] = fmaxf(rm[j], __shfl_xor_sync(0xffffffffu, rm[j], 1));
        rm[j] = fmaxf(rm[j], __shfl_xor_sync(0xffffffffu, rm[j], 2));
    }
    float* smax = (float*)(smem + SM_MAX);
    if ((lane & 3) == 0) {
#pragma unroll
        for (int mf = 0; mf < 4; ++mf) {
            int rloc = warp_m * 64 + mf * 16 + (lane >> 2);
            smax[warp_n * 128 + rloc]     = rm[mf * 2];
            smax[warp_n * 128 + rloc + 8] = rm[mf * 2 + 1];
        }
    }
    __syncthreads();
    if (tid < 128) {
        int row = row0 + tid;
        if (row < ni) {
            float m = fmaxf(fmaxf(smax[tid], smax[128 + tid]),
                            fmaxf(smax[256 + tid], smax[384 + tid]));
            atomicMax(&g_rmax[b * N_ + row], enc_max(m));
        }
    }
}

// ---------------- rescore: bitmask scan, 4-wide ILP exact fp32 dots -------
// 8 warps per CTA, one warp per invalid row. Extract ALL candidates into
// the per-warp list first, then process 4 columns per iteration so the
// load->fma->shfl chains overlap.
__global__ __launch_bounds__(256) void rescore_kernel() {
    __shared__ unsigned short sbuf[8][1060];
    __shared__ int scnt[8];
    int wl = threadIdx.x >> 5, lane = threadIdx.x & 31;
    int gw = blockIdx.x * 8 + wl;
    if (gw >= B_ * N_) return;
    int b = gw / N_, row = gw - b * N_;
    int ni = g_ninv[b], nv = g_nval[b];
    if (row >= ni || nv <= 0) return;

    float m = dec_max(g_rmax[b * N_ + row]);
    if (!(m > SKIP_M)) return;   // true max certainly <= 0.8

    const unsigned* bmr = g_bm + ((size_t)b * N_ + row) * NW;
    int limit_w = (nv + 31) >> 5;

    if (lane == 0) scnt[wl] = 0;
    __syncwarp();
    // extract all candidates (lane-parallel over words)
    for (int wi = lane; wi < limit_w; wi += 32) {
        unsigned w = bmr[wi];
        while (w) {
            int bit = __ffs(w) - 1;
            w &= w - 1;
            int i = atomicAdd(&scnt[wl], 1);
            sbuf[wl][i] = (unsigned short)(wi * 32 + bit);
        }
    }
    __syncwarp();
    int cnt = scnt[wl];
    if (cnt == 0) return;

    const float* rf = g_Rf + ((size_t)b * N_ + row) * D_;
    float4 r0 = ((const float4*)rf)[lane];
    float4 r1 = ((const float4*)rf)[lane + 32];
    const float* vb = g_Vf + (size_t)b * N_ * D_;

    float best = -INFINITY;
    int c = 0;
    for (; c + 4 <= cnt; c += 4) {
        const float4* vc[4];
#pragma unroll
        for (int u = 0; u < 4; ++u)
            vc[u] = (const float4*)(vb + (size_t)sbuf[wl][c + u] * D_);
        float s[4];
#pragma unroll
        for (int u = 0; u < 4; ++u)
            s[u] = dot8(vc[u][lane], vc[u][lane + 32], r0, r1);
#pragma unroll
        for (int o = 16; o; o >>= 1)
#pragma unroll
            for (int u = 0; u < 4; ++u)
                s[u] += __shfl_xor_sync(0xffffffffu, s[u], o);
        best = fmaxf(best, fmaxf(fmaxf(s[0], s[1]), fmaxf(s[2], s[3])));
    }
    for (; c < cnt; ++c) {
        const float4* vc = (const float4*)(vb + (size_t)sbuf[wl][c] * D_);
        float s = dot8(vc[lane], vc[lane + 32], r0, r1);
#pragma unroll
        for (int o = 16; o; o >>= 1)
            s += __shfl_xor_sync(0xffffffffu, s, o);
        best = fmaxf(best, s);
    }
    if (lane == 0 && best > CONF_THRESH) {
        atomicAdd(&g_contrib[b], (double)(1.0f - best));
        atomicAdd(&g_nconf[b], 1);
    }
}

// ---------------- finalize ----------------
__global__ void finalize_kernel(float* out) {
    if (threadIdx.x == 0 && blockIdx.x == 0) {
        double tl = 0.0, tp = 0.0;
        for (int b = 0; b < B_; ++b) {
            int ni = g_ninv[b], nvv = g_nval[b], nc = g_nconf[b];
            bool active = (nc > 0) && (nvv > 0) && (ni > 0);
            if (active) {
                double pseudo = g_contrib[b] / (double)(nc > 1 ? nc : 1);
                tl += pseudo * (double)ni;
                tp += (double)ni;
            }
        }
        out[0] = (tp > 0.0) ? (float)(0.01 * tl / tp) : 0.0f;
    }
}

// ---------------- launch ----------------
extern "C" void kernel_launch(void* const* d_in, const int* in_sizes, int n_in,
                              void* d_out, int out_size) {
    int fi = 0, mi = 1;
    if (n_in >= 2 && in_sizes[0] < in_sizes[1]) { fi = 1; mi = 0; }
    const float* feat = (const float*)d_in[fi];
    const void*  mask = d_in[mi];

    cudaFuncSetAttribute(maxsim_p1, cudaFuncAttributeMaxDynamicSharedMemorySize,
                         SMEM_BYTES);

    init_kernel<<<(B_ * N_ + 255) / 256, 256>>>();
    zero_tiles_kernel<<<592, 256>>>();
    detect_kernel<<<1, 1024>>>((const unsigned char*)mask);
    norm_compact_kernel<<<(B_ * N_ * 32 + 255) / 256, 256>>>(feat, mask);
    dim3 g(N_ / 128, B_, JSPLIT);
    maxsim_p1<<<g, 256, SMEM_BYTES>>>();
    rescore_kernel<<<(B_ * N_ + 7) / 8, 256>>>();
    finalize_kernel<<<1, 32>>>((float*)d_out);
}